// round 5
// baseline (speedup 1.0000x reference)
#include <cuda_runtime.h>
#include <cuda_fp16.h>
#include <cuda_bf16.h>
#include <cstdint>

// y[16,8192] = x[16,8192] @ dequant_q8_0(W)[8192,8192]^T + bias[8192]
// Q8_0 block: 2-byte fp16 scale + 32 int8 -> 34 bytes; 256 blocks/row; 8704 B/row.
//
// The harness may have widened the uint8 weight bytes to a larger dtype.
// probe_kernel detects the on-device encoding; repack_kernel canonicalizes to
// raw GGML bytes in g_wbytes every call (deterministic, graph-safe, no alloc).

#define IN_F      8192
#define OUT_F     8192
#define BATCH     16
#define ROW_BYTES 8704
#define NBYTES    (OUT_F * (IN_F / 32) * 34)   // 71303168
#define NSPLIT    4
#define KSPLIT    (IN_F / NSPLIT)              // 2048
#define CHUNK_K   256
#define CHUNKS    (KSPLIT / CHUNK_K)           // 8

__device__ int     g_mode;
__device__ __align__(16) uint8_t g_wbytes[NBYTES];        // 68 MB canonical bytes
__device__ float   g_partial[NSPLIT][BATCH][OUT_F];       // 2 MB

// ---------------------------------------------------------------------------
// Probe: classify weight buffer encoding from its first 4096 32-bit words.
//   mode 0: raw uint8 bytes (GGML layout as-is)
//   mode 1: widened to int32   (one byte value 0..255 per 4 bytes)
//   mode 2: widened to float32 (values 0.0..255.0)
//   mode 3: widened to bfloat16
//   mode 4: widened to float16
// ---------------------------------------------------------------------------
__global__ void probe_kernel(const uint32_t* __restrict__ qw) {
    __shared__ int ok[4];   // i32, f32, bf16, f16
    int t = threadIdx.x;
    if (t < 4) ok[t] = 1;
    __syncthreads();
    for (int i = t; i < 4096; i += blockDim.x) {
        uint32_t w = qw[i];
        if (w > 255u) ok[0] = 0;
        float f = __uint_as_float(w);
        if (!(f >= 0.f && f <= 255.f && f == floorf(f))) ok[1] = 0;
        float b0 = __bfloat162float(__ushort_as_bfloat16((uint16_t)(w & 0xFFFFu)));
        float b1 = __bfloat162float(__ushort_as_bfloat16((uint16_t)(w >> 16)));
        if (!(b0 >= 0.f && b0 <= 255.f && b0 == floorf(b0) &&
              b1 >= 0.f && b1 <= 255.f && b1 == floorf(b1))) ok[2] = 0;
        float h0 = __half2float(__ushort_as_half((uint16_t)(w & 0xFFFFu)));
        float h1 = __half2float(__ushort_as_half((uint16_t)(w >> 16)));
        if (!(h0 >= 0.f && h0 <= 255.f && h0 == floorf(h0) &&
              h1 >= 0.f && h1 <= 255.f && h1 == floorf(h1))) ok[3] = 0;
    }
    __syncthreads();
    if (t == 0) {
        int m = 0;
        if (ok[0]) m = 1;          // priority: i32 strictest, then f32, bf16, f16
        else if (ok[1]) m = 2;
        else if (ok[2]) m = 3;
        else if (ok[3]) m = 4;
        g_mode = m;
    }
}

// ---------------------------------------------------------------------------
// Repack: canonicalize to raw bytes. One thread = 4 output bytes.
// ---------------------------------------------------------------------------
__global__ void repack_kernel(const void* __restrict__ qw) {
    const int mode = g_mode;
    uint32_t i = blockIdx.x * blockDim.x + threadIdx.x;
    if (i >= NBYTES / 4) return;
    uint32_t w;
    if (mode == 1) {
        int4 v = ((const int4*)qw)[i];
        w = (uint32_t)(v.x & 0xFF) | ((uint32_t)(v.y & 0xFF) << 8)
          | ((uint32_t)(v.z & 0xFF) << 16) | ((uint32_t)(v.w & 0xFF) << 24);
    } else if (mode == 2) {
        float4 v = ((const float4*)qw)[i];
        w = ((uint32_t)(int)v.x & 0xFF) | (((uint32_t)(int)v.y & 0xFF) << 8)
          | (((uint32_t)(int)v.z & 0xFF) << 16) | (((uint32_t)(int)v.w & 0xFF) << 24);
    } else if (mode == 3) {
        const __nv_bfloat16* p = (const __nv_bfloat16*)qw + 4 * (size_t)i;
        w = ((uint32_t)(int)__bfloat162float(p[0]) & 0xFF)
          | (((uint32_t)(int)__bfloat162float(p[1]) & 0xFF) << 8)
          | (((uint32_t)(int)__bfloat162float(p[2]) & 0xFF) << 16)
          | (((uint32_t)(int)__bfloat162float(p[3]) & 0xFF) << 24);
    } else if (mode == 4) {
        const __half* p = (const __half*)qw + 4 * (size_t)i;
        w = ((uint32_t)(int)__half2float(p[0]) & 0xFF)
          | (((uint32_t)(int)__half2float(p[1]) & 0xFF) << 8)
          | (((uint32_t)(int)__half2float(p[2]) & 0xFF) << 16)
          | (((uint32_t)(int)__half2float(p[3]) & 0xFF) << 24);
    } else {
        w = ((const uint32_t*)qw)[i];
    }
    ((uint32_t*)g_wbytes)[i] = w;
}

// ---------------------------------------------------------------------------
// GEMM: pure fp32 FFMA path (auditable). grid (64, 4), 256 threads.
// CTA: 128 output rows x 16 batches; thread: 2 rows x 4 batches.
// xs transposed [k][batch] so each thread reads one float4 per k.
// ---------------------------------------------------------------------------
__global__ __launch_bounds__(256) void gemm_simple(const float* __restrict__ x) {
    __shared__ __align__(16) float xs[CHUNK_K][BATCH + 4];   // 20 KB

    const int t  = threadIdx.x;
    const int tx = t & 3;
    const int ty = t >> 2;                 // 0..63
    const int s  = blockIdx.y;
    const int obase = blockIdx.x * 128;
    const int o0 = obase + 2 * ty;
    const int o1 = o0 + 1;
    const int b0 = 4 * tx;

    const uint8_t* r0 = g_wbytes + (size_t)o0 * ROW_BYTES;
    const uint8_t* r1 = g_wbytes + (size_t)o1 * ROW_BYTES;

    float acc0[4] = {0.f,0.f,0.f,0.f};
    float acc1[4] = {0.f,0.f,0.f,0.f};

    const int kw0 = s * KSPLIT;

    for (int ch = 0; ch < CHUNKS; ++ch) {
        const int kw = kw0 + ch * CHUNK_K;

        __syncthreads();
        #pragma unroll
        for (int b = 0; b < BATCH; ++b)          // coalesced: lane = k
            xs[t][b] = x[b * IN_F + kw + t];
        __syncthreads();

        #pragma unroll
        for (int bl = 0; bl < CHUNK_K / 32; ++bl) {
            const int blk = (kw >> 5) + bl;
            const size_t boff = (size_t)blk * 34;

            const float d0 = __half2float(*reinterpret_cast<const __half*>(r0 + boff));
            const float d1 = __half2float(*reinterpret_cast<const __half*>(r1 + boff));
            const char* q0 = reinterpret_cast<const char*>(r0 + boff + 2);
            const char* q1 = reinterpret_cast<const char*>(r1 + boff + 2);

            float s0[4] = {0.f,0.f,0.f,0.f};
            float s1[4] = {0.f,0.f,0.f,0.f};

            #pragma unroll
            for (int k2 = 0; k2 < 16; ++k2) {
                char2 c0 = *reinterpret_cast<const char2*>(q0 + 2 * k2);
                char2 c1 = *reinterpret_cast<const char2*>(q1 + 2 * k2);
                const float w00 = (float)c0.x, w01 = (float)c0.y;
                const float w10 = (float)c1.x, w11 = (float)c1.y;
                const int kk = bl * 32 + 2 * k2;
                float4 xa = *reinterpret_cast<const float4*>(&xs[kk][b0]);
                float4 xb = *reinterpret_cast<const float4*>(&xs[kk + 1][b0]);
                s0[0] = fmaf(w00, xa.x, s0[0]); s0[0] = fmaf(w01, xb.x, s0[0]);
                s0[1] = fmaf(w00, xa.y, s0[1]); s0[1] = fmaf(w01, xb.y, s0[1]);
                s0[2] = fmaf(w00, xa.z, s0[2]); s0[2] = fmaf(w01, xb.z, s0[2]);
                s0[3] = fmaf(w00, xa.w, s0[3]); s0[3] = fmaf(w01, xb.w, s0[3]);
                s1[0] = fmaf(w10, xa.x, s1[0]); s1[0] = fmaf(w11, xb.x, s1[0]);
                s1[1] = fmaf(w10, xa.y, s1[1]); s1[1] = fmaf(w11, xb.y, s1[1]);
                s1[2] = fmaf(w10, xa.z, s1[2]); s1[2] = fmaf(w11, xb.z, s1[2]);
                s1[3] = fmaf(w10, xa.w, s1[3]); s1[3] = fmaf(w11, xb.w, s1[3]);
            }
            #pragma unroll
            for (int j = 0; j < 4; ++j) {
                acc0[j] = fmaf(d0, s0[j], acc0[j]);
                acc1[j] = fmaf(d1, s1[j], acc1[j]);
            }
        }
    }

    #pragma unroll
    for (int j = 0; j < 4; ++j) {
        g_partial[s][b0 + j][o0] = acc0[j];
        g_partial[s][b0 + j][o1] = acc1[j];
    }
}

// ---------------------------------------------------------------------------
// split-K reduce + bias (deterministic order)
// ---------------------------------------------------------------------------
__global__ void reduce_kernel(const float* __restrict__ bias, float* __restrict__ out) {
    int i = blockIdx.x * blockDim.x + threadIdx.x;
    if (i >= BATCH * OUT_F) return;
    int n = i & (OUT_F - 1);
    const float* p = &g_partial[0][0][0];
    float v = bias[n];
    v += p[i];
    v += p[i + 1 * BATCH * OUT_F];
    v += p[i + 2 * BATCH * OUT_F];
    v += p[i + 3 * BATCH * OUT_F];
    out[i] = v;
}

// ---------------------------------------------------------------------------
extern "C" void kernel_launch(void* const* d_in, const int* in_sizes, int n_in,
                              void* d_out, int out_size) {
    // Identify inputs by SIZE RANK (valid for element or byte counts):
    //   quantized_weight (largest) > x (middle) > bias (smallest)
    int iq = 0, ix = 0, ib = 0;
    for (int i = 1; i < n_in; ++i) if (in_sizes[i] > in_sizes[iq]) iq = i;
    ib = (iq == 0) ? 1 : 0;
    for (int i = 0; i < n_in; ++i)
        if (i != iq && in_sizes[i] < in_sizes[ib]) ib = i;
    for (int i = 0; i < n_in; ++i)
        if (i != iq && i != ib) { ix = i; break; }

    const void*  qw   = d_in[iq];
    const float* x    = (const float*)d_in[ix];
    const float* bias = (const float*)d_in[ib];
    float* out = (float*)d_out;

    probe_kernel<<<1, 256>>>((const uint32_t*)qw);
    repack_kernel<<<(NBYTES / 4 + 255) / 256, 256>>>(qw);
    gemm_simple<<<dim3(OUT_F / 128, NSPLIT), 256>>>(x);
    reduce_kernel<<<(BATCH * OUT_F + 255) / 256, 256>>>(bias, out);
}

// round 6
// speedup vs baseline: 1.5880x; 1.5880x over previous
#include <cuda_runtime.h>
#include <cuda_fp16.h>
#include <cuda_bf16.h>
#include <cstdint>

// y[16,8192] = x[16,8192] @ dequant_q8_0(W)[8192,8192]^T + bias[8192]
// Q8_0 block: 2-byte fp16 scale + 32 int8 -> 34 bytes; 256 blocks/row (8704 B).
//
// The harness delivers quantized_weight WIDENED to some dtype (confirmed R5).
// probe classifies the encoding into g_mode; the MMA GEMM reads the widened
// buffer directly with mode-templated loaders (no repack round-trip).

#define IN_F      8192
#define OUT_F     8192
#define BATCH     16
#define ROW_ELEMS 8704          // GGML byte-stream elements per output row
#define NSPLIT    4
#define BLOCKS_PER_SPLIT 64     // 256 k-blocks / 4

__device__ int    g_mode;
__device__ __half g_x16[BATCH * IN_F];                 // 256 KB
__device__ float  g_partial[NSPLIT][BATCH][OUT_F];     // 2 MB

// ---------------------------------------------------------------------------
// Kernel 1: convert x to f16 (blocks 0..511) + probe weight encoding (block 512)
//   mode 0: raw uint8 bytes        mode 1: widened int32
//   mode 2: widened float32        mode 3: bfloat16     mode 4: float16
// ---------------------------------------------------------------------------
__global__ void convert_probe_kernel(const float* __restrict__ x,
                                     const uint32_t* __restrict__ qw) {
    if (blockIdx.x < 512) {
        int i = blockIdx.x * 256 + threadIdx.x;
        g_x16[i] = __float2half(x[i]);
        return;
    }
    // ---- probe (identical logic to the R5 version that passed) ----
    __shared__ int ok[4];   // i32, f32, bf16, f16
    int t = threadIdx.x;
    if (t < 4) ok[t] = 1;
    __syncthreads();
    for (int i = t; i < 4096; i += blockDim.x) {
        uint32_t w = qw[i];
        if (w > 255u) ok[0] = 0;
        float f = __uint_as_float(w);
        if (!(f >= 0.f && f <= 255.f && f == floorf(f))) ok[1] = 0;
        float b0 = __bfloat162float(__ushort_as_bfloat16((uint16_t)(w & 0xFFFFu)));
        float b1 = __bfloat162float(__ushort_as_bfloat16((uint16_t)(w >> 16)));
        if (!(b0 >= 0.f && b0 <= 255.f && b0 == floorf(b0) &&
              b1 >= 0.f && b1 <= 255.f && b1 == floorf(b1))) ok[2] = 0;
        float h0 = __half2float(__ushort_as_half((uint16_t)(w & 0xFFFFu)));
        float h1 = __half2float(__ushort_as_half((uint16_t)(w >> 16)));
        if (!(h0 >= 0.f && h0 <= 255.f && h0 == floorf(h0) &&
              h1 >= 0.f && h1 <= 255.f && h1 == floorf(h1))) ok[3] = 0;
    }
    __syncthreads();
    if (t == 0) {
        int m = 0;
        if (ok[0]) m = 1;
        else if (ok[1]) m = 2;
        else if (ok[2]) m = 3;
        else if (ok[3]) m = 4;
        g_mode = m;
    }
}

// ---------------------------------------------------------------------------
// Mode-templated loaders. eoff is an offset in GGML-byte-stream ELEMENTS.
// Byte recovery matches the R5 repack exactly (low-byte masking handles both
// signed and unsigned widening).
// ---------------------------------------------------------------------------
template<int M>
__device__ __forceinline__ uint32_t load_q4(const uint8_t* p, size_t eoff) {
    // packs bytes {e, e+1, e+8, e+9} little-endian into one u32
    if (M == 0) {
        uint32_t lo = *reinterpret_cast<const uint16_t*>(p + eoff);
        uint32_t hi = *reinterpret_cast<const uint16_t*>(p + eoff + 8);
        return lo | (hi << 16);
    } else if (M == 1) {
        int2 a = *reinterpret_cast<const int2*>(p + eoff * 4);
        int2 b = *reinterpret_cast<const int2*>(p + (eoff + 8) * 4);
        return (uint32_t)(a.x & 0xFF) | ((uint32_t)(a.y & 0xFF) << 8)
             | ((uint32_t)(b.x & 0xFF) << 16) | ((uint32_t)(b.y & 0xFF) << 24);
    } else if (M == 2) {
        float2 a = *reinterpret_cast<const float2*>(p + eoff * 4);
        float2 b = *reinterpret_cast<const float2*>(p + (eoff + 8) * 4);
        return ((uint32_t)(int)a.x & 0xFF) | (((uint32_t)(int)a.y & 0xFF) << 8)
             | (((uint32_t)(int)b.x & 0xFF) << 16) | (((uint32_t)(int)b.y & 0xFF) << 24);
    } else if (M == 3) {
        const __nv_bfloat16* q = reinterpret_cast<const __nv_bfloat16*>(p);
        return ((uint32_t)(int)__bfloat162float(q[eoff])     & 0xFF)
             | (((uint32_t)(int)__bfloat162float(q[eoff + 1]) & 0xFF) << 8)
             | (((uint32_t)(int)__bfloat162float(q[eoff + 8]) & 0xFF) << 16)
             | (((uint32_t)(int)__bfloat162float(q[eoff + 9]) & 0xFF) << 24);
    } else {
        const __half* q = reinterpret_cast<const __half*>(p);
        return ((uint32_t)(int)__half2float(q[eoff])     & 0xFF)
             | (((uint32_t)(int)__half2float(q[eoff + 1]) & 0xFF) << 8)
             | (((uint32_t)(int)__half2float(q[eoff + 8]) & 0xFF) << 16)
             | (((uint32_t)(int)__half2float(q[eoff + 9]) & 0xFF) << 24);
    }
}

template<int M>
__device__ __forceinline__ float load_scale(const uint8_t* p, size_t eoff) {
    uint16_t bits;
    if (M == 0) {
        bits = *reinterpret_cast<const uint16_t*>(p + eoff);
    } else if (M == 1) {
        int2 a = *reinterpret_cast<const int2*>(p + eoff * 4);
        bits = (uint16_t)((a.x & 0xFF) | ((a.y & 0xFF) << 8));
    } else if (M == 2) {
        float2 a = *reinterpret_cast<const float2*>(p + eoff * 4);
        bits = (uint16_t)(((int)a.x & 0xFF) | (((int)a.y & 0xFF) << 8));
    } else if (M == 3) {
        const __nv_bfloat16* q = reinterpret_cast<const __nv_bfloat16*>(p);
        bits = (uint16_t)(((int)__bfloat162float(q[eoff]) & 0xFF)
                        | (((int)__bfloat162float(q[eoff + 1]) & 0xFF) << 8));
    } else {
        const __half* q = reinterpret_cast<const __half*>(p);
        bits = (uint16_t)(((int)__half2float(q[eoff]) & 0xFF)
                        | (((int)__half2float(q[eoff + 1]) & 0xFF) << 8));
    }
    return __half2float(__ushort_as_half(bits));
}

// ---------------------------------------------------------------------------
// mma.sync m16n8k16 f16 -> f32
// ---------------------------------------------------------------------------
__device__ __forceinline__ void mma16816(float c[4], const uint32_t a[4],
                                         uint32_t b0, uint32_t b1) {
    asm volatile(
        "mma.sync.aligned.m16n8k16.row.col.f32.f16.f16.f32 "
        "{%0,%1,%2,%3}, {%4,%5,%6,%7}, {%8,%9}, {%0,%1,%2,%3};\n"
        : "+f"(c[0]), "+f"(c[1]), "+f"(c[2]), "+f"(c[3])
        : "r"(a[0]), "r"(a[1]), "r"(a[2]), "r"(a[3]), "r"(b0), "r"(b1));
}

// u32 of 4 quant bytes {k,k+1,k+8,k+9} -> two f16x2 regs with EXACT integer q.
__device__ __forceinline__ void make_bfrag(uint32_t u, uint32_t& w0, uint32_t& w1) {
    u ^= 0x80808080u;                                         // int8 -> biased u8
    uint32_t r0 = __byte_perm(u, 0x64646464u, 0x4140);        // {1024+b0, 1024+b1}
    uint32_t r1 = __byte_perm(u, 0x64646464u, 0x4342);        // {1024+b2, 1024+b3}
    const __half2 magic = __halves2half2(__ushort_as_half(0x6480),   // 1152.0
                                         __ushort_as_half(0x6480));
    __half2 h0 = __hsub2(*reinterpret_cast<__half2*>(&r0), magic);   // exact q
    __half2 h1 = __hsub2(*reinterpret_cast<__half2*>(&r1), magic);
    w0 = *reinterpret_cast<uint32_t*>(&h0);
    w1 = *reinterpret_cast<uint32_t*>(&h1);
}

// ---------------------------------------------------------------------------
// GEMM body: grid (128 col-tiles, 4 k-splits), 128 threads (4 warps).
// Warp covers 16 cols (two 8-col B tiles). Scale folded in fp32 post-MMA.
// ---------------------------------------------------------------------------
template<int M>
__device__ __forceinline__ void gemm_body(const uint8_t* __restrict__ qw) {
    const int warp = threadIdx.x >> 5;
    const int lane = threadIdx.x & 31;
    const int g = lane >> 2;     // groupID (0..7)
    const int t = lane & 3;      // thread-in-group (0..3)
    const int s = blockIdx.y;
    const int n0 = blockIdx.x * 64 + warp * 16;

    const int blk_begin = s * BLOCKS_PER_SPLIT;
    const int blk_end   = blk_begin + BLOCKS_PER_SPLIT;

    // element-offset row bases (GGML stream elements)
    const size_t rq0 = (size_t)(n0 + g) * ROW_ELEMS;          // quant rows
    const size_t rq1 = (size_t)(n0 + 8 + g) * ROW_ELEMS;
    const size_t rs0 = (size_t)(n0 + 2 * t) * ROW_ELEMS;      // scale rows
    const size_t rs1 = rs0 + ROW_ELEMS;
    const size_t rs2 = (size_t)(n0 + 8 + 2 * t) * ROW_ELEMS;
    const size_t rs3 = rs2 + ROW_ELEMS;

    const __half* xr0 = g_x16 + g * IN_F + 2 * t;
    const __half* xr1 = xr0 + 8 * IN_F;

    float c0[4] = {0.f, 0.f, 0.f, 0.f};
    float c1[4] = {0.f, 0.f, 0.f, 0.f};

    #pragma unroll 2
    for (int blk = blk_begin; blk < blk_end; ++blk) {
        const size_t boff = (size_t)blk * 34;
        const size_t qoff = boff + 2 + 2 * t;
        const int kbase = blk * 32;

        const float d0 = load_scale<M>(qw, rs0 + boff);
        const float d1 = load_scale<M>(qw, rs1 + boff);
        const float d2 = load_scale<M>(qw, rs2 + boff);
        const float d3 = load_scale<M>(qw, rs3 + boff);

        float cb0[4] = {0.f, 0.f, 0.f, 0.f};
        float cb1[4] = {0.f, 0.f, 0.f, 0.f};

        #pragma unroll
        for (int kin = 0; kin < 32; kin += 16) {
            uint32_t a[4];
            const __half* p0 = xr0 + kbase + kin;
            const __half* p1 = xr1 + kbase + kin;
            a[0] = *reinterpret_cast<const uint32_t*>(p0);
            a[1] = *reinterpret_cast<const uint32_t*>(p1);
            a[2] = *reinterpret_cast<const uint32_t*>(p0 + 8);
            a[3] = *reinterpret_cast<const uint32_t*>(p1 + 8);

            uint32_t w0, w1;
            make_bfrag(load_q4<M>(qw, rq0 + qoff + kin), w0, w1);
            mma16816(cb0, a, w0, w1);
            make_bfrag(load_q4<M>(qw, rq1 + qoff + kin), w0, w1);
            mma16816(cb1, a, w0, w1);
        }

        c0[0] = fmaf(d0, cb0[0], c0[0]);
        c0[1] = fmaf(d1, cb0[1], c0[1]);
        c0[2] = fmaf(d0, cb0[2], c0[2]);
        c0[3] = fmaf(d1, cb0[3], c0[3]);
        c1[0] = fmaf(d2, cb1[0], c1[0]);
        c1[1] = fmaf(d3, cb1[1], c1[1]);
        c1[2] = fmaf(d2, cb1[2], c1[2]);
        c1[3] = fmaf(d3, cb1[3], c1[3]);
    }

    int col = n0 + 2 * t;
    *reinterpret_cast<float2*>(&g_partial[s][g][col])     = make_float2(c0[0], c0[1]);
    *reinterpret_cast<float2*>(&g_partial[s][g + 8][col]) = make_float2(c0[2], c0[3]);
    col += 8;
    *reinterpret_cast<float2*>(&g_partial[s][g][col])     = make_float2(c1[0], c1[1]);
    *reinterpret_cast<float2*>(&g_partial[s][g + 8][col]) = make_float2(c1[2], c1[3]);
}

__global__ __launch_bounds__(128) void gemm_kernel(const uint8_t* __restrict__ qw) {
    const int mode = g_mode;      // uniform across grid
    if      (mode == 1) gemm_body<1>(qw);
    else if (mode == 2) gemm_body<2>(qw);
    else if (mode == 0) gemm_body<0>(qw);
    else if (mode == 3) gemm_body<3>(qw);
    else                gemm_body<4>(qw);
}

// ---------------------------------------------------------------------------
// split-K reduce + bias (deterministic, vectorized)
// ---------------------------------------------------------------------------
__global__ void reduce_kernel(const float* __restrict__ bias, float* __restrict__ out) {
    int i4 = blockIdx.x * blockDim.x + threadIdx.x;         // float4 index
    if (i4 >= (BATCH * OUT_F) / 4) return;
    int i = i4 * 4;
    int n = i & (OUT_F - 1);
    const float* p = &g_partial[0][0][0];
    float4 v  = *reinterpret_cast<const float4*>(bias + n);
    float4 a0 = *reinterpret_cast<const float4*>(p + i);
    float4 a1 = *reinterpret_cast<const float4*>(p + i + 1 * BATCH * OUT_F);
    float4 a2 = *reinterpret_cast<const float4*>(p + i + 2 * BATCH * OUT_F);
    float4 a3 = *reinterpret_cast<const float4*>(p + i + 3 * BATCH * OUT_F);
    v.x += a0.x + a1.x + a2.x + a3.x;
    v.y += a0.y + a1.y + a2.y + a3.y;
    v.z += a0.z + a1.z + a2.z + a3.z;
    v.w += a0.w + a1.w + a2.w + a3.w;
    *reinterpret_cast<float4*>(out + i) = v;
}

// ---------------------------------------------------------------------------
extern "C" void kernel_launch(void* const* d_in, const int* in_sizes, int n_in,
                              void* d_out, int out_size) {
    // Identify inputs by SIZE RANK (valid for element or byte counts):
    //   quantized_weight (largest) > x (middle) > bias (smallest)
    int iq = 0, ix = 0, ib = 0;
    for (int i = 1; i < n_in; ++i) if (in_sizes[i] > in_sizes[iq]) iq = i;
    ib = (iq == 0) ? 1 : 0;
    for (int i = 0; i < n_in; ++i)
        if (i != iq && in_sizes[i] < in_sizes[ib]) ib = i;
    for (int i = 0; i < n_in; ++i)
        if (i != iq && i != ib) { ix = i; break; }

    const uint8_t* qw   = (const uint8_t*)d_in[iq];
    const float*   x    = (const float*)d_in[ix];
    const float*   bias = (const float*)d_in[ib];
    float* out = (float*)d_out;

    convert_probe_kernel<<<513, 256>>>(x, (const uint32_t*)qw);
    gemm_kernel<<<dim3(OUT_F / 64, NSPLIT), 128>>>(qw);
    reduce_kernel<<<(BATCH * OUT_F / 4 + 255) / 256, 256>>>(bias, out);
}

// round 7
// speedup vs baseline: 1.6792x; 1.0575x over previous
#include <cuda_runtime.h>
#include <cuda_fp16.h>
#include <cuda_bf16.h>
#include <cstdint>

// y[16,8192] = x[16,8192] @ dequant_q8_0(W)[8192,8192]^T + bias[8192]
// Q8_0 block: 2-byte fp16 scale + 32 int8 -> 34 "bytes"; 256 blocks/row.
// quantized_weight arrives WIDENED to an unknown dtype (probed at runtime);
// all loaders are mode-templated and consume the widened buffer directly.

#define IN_F      8192
#define OUT_F     8192
#define BATCH     16
#define ROW_ELEMS 8704
#define NSPLIT    8
#define BLOCKS_PER_SPLIT 32     // 256 k-blocks / 8
#define KSPLIT    1024

__device__ int    g_mode;
__device__ __half g_x16[BATCH * IN_F];                 // 256 KB
__device__ float  g_partial[NSPLIT][BATCH][OUT_F];     // 4 MB

// ---------------------------------------------------------------------------
// Kernel 1: convert x to f16 (blocks 0..127, float4-vectorized) + probe (block 128)
//   mode 0: raw bytes  1: int32  2: float32  3: bfloat16  4: float16
// ---------------------------------------------------------------------------
__global__ void convert_probe_kernel(const float* __restrict__ x,
                                     const uint32_t* __restrict__ qw) {
    if (blockIdx.x < 128) {
        int i4 = blockIdx.x * 256 + threadIdx.x;        // float4 index
        float4 v = *reinterpret_cast<const float4*>(x + i4 * 4);
        __half2 h0 = __floats2half2_rn(v.x, v.y);
        __half2 h1 = __floats2half2_rn(v.z, v.w);
        uint2 w;
        w.x = *reinterpret_cast<uint32_t*>(&h0);
        w.y = *reinterpret_cast<uint32_t*>(&h1);
        *reinterpret_cast<uint2*>(&g_x16[i4 * 4]) = w;
        return;
    }
    __shared__ int ok[4];   // i32, f32, bf16, f16
    int t = threadIdx.x;
    if (t < 4) ok[t] = 1;
    __syncthreads();
    for (int i = t; i < 4096; i += blockDim.x) {
        uint32_t w = qw[i];
        if (w > 255u) ok[0] = 0;
        float f = __uint_as_float(w);
        if (!(f >= 0.f && f <= 255.f && f == floorf(f))) ok[1] = 0;
        float b0 = __bfloat162float(__ushort_as_bfloat16((uint16_t)(w & 0xFFFFu)));
        float b1 = __bfloat162float(__ushort_as_bfloat16((uint16_t)(w >> 16)));
        if (!(b0 >= 0.f && b0 <= 255.f && b0 == floorf(b0) &&
              b1 >= 0.f && b1 <= 255.f && b1 == floorf(b1))) ok[2] = 0;
        float h0 = __half2float(__ushort_as_half((uint16_t)(w & 0xFFFFu)));
        float h1 = __half2float(__ushort_as_half((uint16_t)(w >> 16)));
        if (!(h0 >= 0.f && h0 <= 255.f && h0 == floorf(h0) &&
              h1 >= 0.f && h1 <= 255.f && h1 == floorf(h1))) ok[3] = 0;
    }
    __syncthreads();
    if (t == 0) {
        int m = 0;
        if (ok[0]) m = 1;
        else if (ok[1]) m = 2;
        else if (ok[2]) m = 3;
        else if (ok[3]) m = 4;
        g_mode = m;
    }
}

// ---------------------------------------------------------------------------
// Raw (pre-pack) load containers: loads issue at fetch, ALU deferred to pack.
// ---------------------------------------------------------------------------
template<int M> struct QRaw { uint32_t w[(M == 0) ? 1 : ((M <= 2) ? 4 : 2)]; };
template<int M> struct SRaw { uint32_t w[(M == 0) ? 1 : ((M <= 2) ? 2 : 1)]; };

// quant bytes {e, e+1, e+8, e+9} of the GGML stream
template<int M>
__device__ __forceinline__ QRaw<M> fetch_q4(const uint8_t* __restrict__ p, size_t e) {
    QRaw<M> r;
    if constexpr (M == 0) {
        uint32_t lo = *reinterpret_cast<const uint16_t*>(p + e);
        uint32_t hi = *reinterpret_cast<const uint16_t*>(p + e + 8);
        r.w[0] = lo | (hi << 16);
    } else if constexpr (M == 1 || M == 2) {
        uint2 a = *reinterpret_cast<const uint2*>(p + e * 4);
        uint2 b = *reinterpret_cast<const uint2*>(p + (e + 8) * 4);
        r.w[0] = a.x; r.w[1] = a.y; r.w[2] = b.x; r.w[3] = b.y;
    } else {
        r.w[0] = *reinterpret_cast<const uint32_t*>(p + e * 2);
        r.w[1] = *reinterpret_cast<const uint32_t*>(p + (e + 8) * 2);
    }
    return r;
}

template<int M>
__device__ __forceinline__ uint32_t pack_q4(QRaw<M> r) {
    if constexpr (M == 0) {
        return r.w[0];
    } else if constexpr (M == 1) {
        return (r.w[0] & 0xFFu) | ((r.w[1] & 0xFFu) << 8)
             | ((r.w[2] & 0xFFu) << 16) | ((r.w[3] & 0xFFu) << 24);
    } else if constexpr (M == 2) {
        return ((uint32_t)(int)__uint_as_float(r.w[0]) & 0xFFu)
             | (((uint32_t)(int)__uint_as_float(r.w[1]) & 0xFFu) << 8)
             | (((uint32_t)(int)__uint_as_float(r.w[2]) & 0xFFu) << 16)
             | (((uint32_t)(int)__uint_as_float(r.w[3]) & 0xFFu) << 24);
    } else if constexpr (M == 3) {
        uint32_t b0 = (uint32_t)(int)__bfloat162float(__ushort_as_bfloat16((uint16_t)(r.w[0] & 0xFFFFu))) & 0xFFu;
        uint32_t b1 = (uint32_t)(int)__bfloat162float(__ushort_as_bfloat16((uint16_t)(r.w[0] >> 16)))     & 0xFFu;
        uint32_t b2 = (uint32_t)(int)__bfloat162float(__ushort_as_bfloat16((uint16_t)(r.w[1] & 0xFFFFu))) & 0xFFu;
        uint32_t b3 = (uint32_t)(int)__bfloat162float(__ushort_as_bfloat16((uint16_t)(r.w[1] >> 16)))     & 0xFFu;
        return b0 | (b1 << 8) | (b2 << 16) | (b3 << 24);
    } else {
        uint32_t b0 = (uint32_t)(int)__half2float(__ushort_as_half((uint16_t)(r.w[0] & 0xFFFFu))) & 0xFFu;
        uint32_t b1 = (uint32_t)(int)__half2float(__ushort_as_half((uint16_t)(r.w[0] >> 16)))     & 0xFFu;
        uint32_t b2 = (uint32_t)(int)__half2float(__ushort_as_half((uint16_t)(r.w[1] & 0xFFFFu))) & 0xFFu;
        uint32_t b3 = (uint32_t)(int)__half2float(__ushort_as_half((uint16_t)(r.w[1] >> 16)))     & 0xFFu;
        return b0 | (b1 << 8) | (b2 << 16) | (b3 << 24);
    }
}

// fp16 scale bytes {e, e+1}
template<int M>
__device__ __forceinline__ SRaw<M> fetch_sc(const uint8_t* __restrict__ p, size_t e) {
    SRaw<M> r;
    if constexpr (M == 0) {
        r.w[0] = *reinterpret_cast<const uint16_t*>(p + e);
    } else if constexpr (M == 1 || M == 2) {
        uint2 a = *reinterpret_cast<const uint2*>(p + e * 4);
        r.w[0] = a.x; r.w[1] = a.y;
    } else {
        r.w[0] = *reinterpret_cast<const uint32_t*>(p + e * 2);
    }
    return r;
}

template<int M>
__device__ __forceinline__ float pack_sc(SRaw<M> r) {
    uint16_t bits;
    if constexpr (M == 0) {
        bits = (uint16_t)r.w[0];
    } else if constexpr (M == 1) {
        bits = (uint16_t)((r.w[0] & 0xFFu) | ((r.w[1] & 0xFFu) << 8));
    } else if constexpr (M == 2) {
        bits = (uint16_t)(((int)__uint_as_float(r.w[0]) & 0xFF)
                        | (((int)__uint_as_float(r.w[1]) & 0xFF) << 8));
    } else if constexpr (M == 3) {
        bits = (uint16_t)(((int)__bfloat162float(__ushort_as_bfloat16((uint16_t)(r.w[0] & 0xFFFFu))) & 0xFF)
                        | (((int)__bfloat162float(__ushort_as_bfloat16((uint16_t)(r.w[0] >> 16))) & 0xFF) << 8));
    } else {
        bits = (uint16_t)(((int)__half2float(__ushort_as_half((uint16_t)(r.w[0] & 0xFFFFu))) & 0xFF)
                        | (((int)__half2float(__ushort_as_half((uint16_t)(r.w[0] >> 16))) & 0xFF) << 8));
    }
    return __half2float(__ushort_as_half(bits));
}

// ---------------------------------------------------------------------------
__device__ __forceinline__ void mma16816(float c[4], const uint32_t a[4],
                                         uint32_t b0, uint32_t b1) {
    asm volatile(
        "mma.sync.aligned.m16n8k16.row.col.f32.f16.f16.f32 "
        "{%0,%1,%2,%3}, {%4,%5,%6,%7}, {%8,%9}, {%0,%1,%2,%3};\n"
        : "+f"(c[0]), "+f"(c[1]), "+f"(c[2]), "+f"(c[3])
        : "r"(a[0]), "r"(a[1]), "r"(a[2]), "r"(a[3]), "r"(b0), "r"(b1));
}

// u32 {k,k+1,k+8,k+9} int8 -> two f16x2 regs with EXACT integer q values.
__device__ __forceinline__ void make_bfrag(uint32_t u, uint32_t& w0, uint32_t& w1) {
    u ^= 0x80808080u;
    uint32_t r0 = __byte_perm(u, 0x64646464u, 0x4140);
    uint32_t r1 = __byte_perm(u, 0x64646464u, 0x4342);
    const __half2 magic = __halves2half2(__ushort_as_half(0x6480),
                                         __ushort_as_half(0x6480));   // 1152.0
    __half2 h0 = __hsub2(*reinterpret_cast<__half2*>(&r0), magic);
    __half2 h1 = __hsub2(*reinterpret_cast<__half2*>(&r1), magic);
    w0 = *reinterpret_cast<uint32_t*>(&h0);
    w1 = *reinterpret_cast<uint32_t*>(&h1);
}

// ---------------------------------------------------------------------------
// Pipelined stage: all raw loads for one k-block (quants, scales, A-frags).
// ---------------------------------------------------------------------------
template<int M> struct Stage {
    QRaw<M> q[4];      // {tile0,kin0},{tile1,kin0},{tile0,kin16},{tile1,kin16}
    SRaw<M> s[4];      // scales for cols n0+2t, +1, n0+8+2t, +1
    uint32_t a[8];     // A frags: kin0 x4, kin16 x4
};

struct Ctx {
    const uint8_t* qw;
    size_t rq0, rq1, rs0, rs1, rs2, rs3;   // row bases (GGML elements)
    const __half* xr0;
    const __half* xr1;
    int t;
};

template<int M>
__device__ __forceinline__ void fetch_stage(Stage<M>& st, const Ctx& c, int blk) {
    const size_t boff = (size_t)blk * 34;
    const size_t qo = boff + 2 + 2 * c.t;
    st.q[0] = fetch_q4<M>(c.qw, c.rq0 + qo);
    st.q[1] = fetch_q4<M>(c.qw, c.rq1 + qo);
    st.q[2] = fetch_q4<M>(c.qw, c.rq0 + qo + 16);
    st.q[3] = fetch_q4<M>(c.qw, c.rq1 + qo + 16);
    st.s[0] = fetch_sc<M>(c.qw, c.rs0 + boff);
    st.s[1] = fetch_sc<M>(c.qw, c.rs1 + boff);
    st.s[2] = fetch_sc<M>(c.qw, c.rs2 + boff);
    st.s[3] = fetch_sc<M>(c.qw, c.rs3 + boff);
    const int kbase = blk * 32;
    const __half* p0 = c.xr0 + kbase;
    const __half* p1 = c.xr1 + kbase;
    st.a[0] = *reinterpret_cast<const uint32_t*>(p0);
    st.a[1] = *reinterpret_cast<const uint32_t*>(p1);
    st.a[2] = *reinterpret_cast<const uint32_t*>(p0 + 8);
    st.a[3] = *reinterpret_cast<const uint32_t*>(p1 + 8);
    st.a[4] = *reinterpret_cast<const uint32_t*>(p0 + 16);
    st.a[5] = *reinterpret_cast<const uint32_t*>(p1 + 16);
    st.a[6] = *reinterpret_cast<const uint32_t*>(p0 + 24);
    st.a[7] = *reinterpret_cast<const uint32_t*>(p1 + 24);
}

template<int M>
__device__ __forceinline__ void compute_stage(const Stage<M>& st,
                                              float c0[4], float c1[4]) {
    float cb0[4] = {0.f, 0.f, 0.f, 0.f};
    float cb1[4] = {0.f, 0.f, 0.f, 0.f};
    uint32_t w0, w1;
    make_bfrag(pack_q4<M>(st.q[0]), w0, w1); mma16816(cb0, st.a,     w0, w1);
    make_bfrag(pack_q4<M>(st.q[1]), w0, w1); mma16816(cb1, st.a,     w0, w1);
    make_bfrag(pack_q4<M>(st.q[2]), w0, w1); mma16816(cb0, st.a + 4, w0, w1);
    make_bfrag(pack_q4<M>(st.q[3]), w0, w1); mma16816(cb1, st.a + 4, w0, w1);
    const float d0 = pack_sc<M>(st.s[0]);
    const float d1 = pack_sc<M>(st.s[1]);
    const float d2 = pack_sc<M>(st.s[2]);
    const float d3 = pack_sc<M>(st.s[3]);
    c0[0] = fmaf(d0, cb0[0], c0[0]);
    c0[1] = fmaf(d1, cb0[1], c0[1]);
    c0[2] = fmaf(d0, cb0[2], c0[2]);
    c0[3] = fmaf(d1, cb0[3], c0[3]);
    c1[0] = fmaf(d2, cb1[0], c1[0]);
    c1[1] = fmaf(d3, cb1[1], c1[1]);
    c1[2] = fmaf(d2, cb1[2], c1[2]);
    c1[3] = fmaf(d3, cb1[3], c1[3]);
}

// ---------------------------------------------------------------------------
// GEMM: grid (128 col-tiles, 8 k-splits), 128 threads (4 warps, 16 cols each).
// ---------------------------------------------------------------------------
template<int M>
__device__ __forceinline__ void gemm_body(const uint8_t* __restrict__ qw) {
    const int warp = threadIdx.x >> 5;
    const int lane = threadIdx.x & 31;
    const int g = lane >> 2;
    const int t = lane & 3;
    const int s = blockIdx.y;
    const int n0 = blockIdx.x * 64 + warp * 16;

    Ctx c;
    c.qw  = qw;
    c.t   = t;
    c.rq0 = (size_t)(n0 + g) * ROW_ELEMS;
    c.rq1 = (size_t)(n0 + 8 + g) * ROW_ELEMS;
    c.rs0 = (size_t)(n0 + 2 * t) * ROW_ELEMS;
    c.rs1 = c.rs0 + ROW_ELEMS;
    c.rs2 = (size_t)(n0 + 8 + 2 * t) * ROW_ELEMS;
    c.rs3 = c.rs2 + ROW_ELEMS;
    c.xr0 = g_x16 + g * IN_F + 2 * t;
    c.xr1 = c.xr0 + 8 * IN_F;

    const int blk_begin = s * BLOCKS_PER_SPLIT;
    const int blk_end   = blk_begin + BLOCKS_PER_SPLIT;

    float c0[4] = {0.f, 0.f, 0.f, 0.f};
    float c1[4] = {0.f, 0.f, 0.f, 0.f};

    Stage<M> sA, sB;
    fetch_stage<M>(sA, c, blk_begin);

    #pragma unroll 1
    for (int blk = blk_begin; blk < blk_end; blk += 2) {
        fetch_stage<M>(sB, c, blk + 1);            // in flight during compute(sA)
        compute_stage<M>(sA, c0, c1);
        if (blk + 2 < blk_end)
            fetch_stage<M>(sA, c, blk + 2);        // in flight during compute(sB)
        compute_stage<M>(sB, c0, c1);
    }

    int col = n0 + 2 * t;
    *reinterpret_cast<float2*>(&g_partial[s][g][col])     = make_float2(c0[0], c0[1]);
    *reinterpret_cast<float2*>(&g_partial[s][g + 8][col]) = make_float2(c0[2], c0[3]);
    col += 8;
    *reinterpret_cast<float2*>(&g_partial[s][g][col])     = make_float2(c1[0], c1[1]);
    *reinterpret_cast<float2*>(&g_partial[s][g + 8][col]) = make_float2(c1[2], c1[3]);
}

__global__ __launch_bounds__(128) void gemm_kernel(const uint8_t* __restrict__ qw) {
    const int mode = g_mode;      // uniform
    if      (mode == 1) gemm_body<1>(qw);
    else if (mode == 2) gemm_body<2>(qw);
    else if (mode == 0) gemm_body<0>(qw);
    else if (mode == 3) gemm_body<3>(qw);
    else                gemm_body<4>(qw);
}

// ---------------------------------------------------------------------------
// split-K reduce + bias (deterministic, float4)
// ---------------------------------------------------------------------------
__global__ void reduce_kernel(const float* __restrict__ bias, float* __restrict__ out) {
    int i4 = blockIdx.x * blockDim.x + threadIdx.x;
    if (i4 >= (BATCH * OUT_F) / 4) return;
    int i = i4 * 4;
    int n = i & (OUT_F - 1);
    const float* p = &g_partial[0][0][0];
    float4 v = *reinterpret_cast<const float4*>(bias + n);
    #pragma unroll
    for (int s = 0; s < NSPLIT; ++s) {
        float4 a = *reinterpret_cast<const float4*>(p + i + s * BATCH * OUT_F);
        v.x += a.x; v.y += a.y; v.z += a.z; v.w += a.w;
    }
    *reinterpret_cast<float4*>(out + i) = v;
}

// ---------------------------------------------------------------------------
extern "C" void kernel_launch(void* const* d_in, const int* in_sizes, int n_in,
                              void* d_out, int out_size) {
    // Inputs by SIZE RANK (units-agnostic): qw (largest) > x (middle) > bias.
    int iq = 0, ix = 0, ib = 0;
    for (int i = 1; i < n_in; ++i) if (in_sizes[i] > in_sizes[iq]) iq = i;
    ib = (iq == 0) ? 1 : 0;
    for (int i = 0; i < n_in; ++i)
        if (i != iq && in_sizes[i] < in_sizes[ib]) ib = i;
    for (int i = 0; i < n_in; ++i)
        if (i != iq && i != ib) { ix = i; break; }

    const uint8_t* qw   = (const uint8_t*)d_in[iq];
    const float*   x    = (const float*)d_in[ix];
    const float*   bias = (const float*)d_in[ib];
    float* out = (float*)d_out;

    convert_probe_kernel<<<129, 256>>>(x, (const uint32_t*)qw);
    gemm_kernel<<<dim3(OUT_F / 64, NSPLIT), 128>>>(qw);
    reduce_kernel<<<(BATCH * OUT_F / 4 + 255) / 256, 256>>>(bias, out);
}